// round 16
// baseline (speedup 1.0000x reference)
#include <cuda_runtime.h>
#include <cuda_fp16.h>
#include <math.h>
#include <stdint.h>

#define HW    16384
#define IMW   128
#define IMH   128
#define CC    192
#define NB    8
#define NHEADS 8
#define HD    24
#define CHG   8
#define KQ    (9*CC)            // 1728
#define PADW  130
#define PADHW (IMH*PADW)        // 16640
#define YSLOTS (PADHW + 2*PADW) // guard rows top+bottom

// ---------------- scratch ---------------------------------------------------
__device__ __align__(1024) __half g_xH  [(size_t)NB*HW*CC];
__device__ __align__(1024) __half g_yTpH[(size_t)NB*YSLOTS*CC];
__device__ __align__(1024) __half g_kv1H[(size_t)NB*2*CC*HW];
__device__ __align__(1024) __half g_kH  [(size_t)NB*CC*HW + 16*HW];
__device__ __align__(1024) __half g_vcmH[(size_t)NB*CC*HW];
__device__ __align__(1024) __half g_vH  [(size_t)NB*HW*CC];
__device__ __align__(1024) __half g_qH  [(size_t)NB*CC*HW + 16*HW];
__device__ __align__(1024) __half g_w2H [(size_t)CC*KQ];
__device__ __align__(1024) __half g_kvwH[2*CC*CC];
__device__ __align__(1024) __half g_MoH [(size_t)NB*CC*CC];
__device__ float g_Sp [(size_t)NB*NHEADS*CHG*HD*HD];
__device__ float g_nqF[(size_t)NB*CC];
__device__ float g_nkF[(size_t)NB*CC];

__device__ __forceinline__ uint32_t smem_u32(const void* p) {
    uint32_t a;
    asm("{ .reg .u64 t; cvta.to.shared.u64 t, %1; cvt.u32.u64 %0, t; }"
        : "=r"(a) : "l"(p));
    return a;
}

#define LDSM_X4(r0, r1, r2, r3, addr) \
    asm volatile("ldmatrix.sync.aligned.m8n8.x4.shared.b16 {%0,%1,%2,%3}, [%4];" \
                 : "=r"(r0), "=r"(r1), "=r"(r2), "=r"(r3) : "r"(addr))

#define MMA16816(d, a, b0v, b1v) \
    asm volatile("mma.sync.aligned.m16n8k16.row.col.f32.f16.f16.f32 " \
                 "{%0,%1,%2,%3}, {%4,%5,%6,%7}, {%8,%9}, {%0,%1,%2,%3};" \
                 : "+f"((d)[0]), "+f"((d)[1]), "+f"((d)[2]), "+f"((d)[3]) \
                 : "r"((a)[0]), "r"((a)[1]), "r"((a)[2]), "r"((a)[3]), \
                   "r"(b0v), "r"(b1v))

#define CP16(dst, src) \
    asm volatile("cp.async.cg.shared.global [%0], [%1], 16;" \
                 :: "r"(dst), "l"(src))

// ---------------- fp16 mma GEMM: 128p x 64o tile, BK=64, 4 blocks/SM --------
// C[o][p] = sum_k A[p][k]*B[o][k]; 256 thr, 2-stage cp.async double buffer.
// 8 warps = 4 p-quarters (32 rows) x 2 o-halves (32 cols); acc 2x4x4 = 32.
// Rows stored with 144B stride -> conflict-free ldmatrix.
// conv_mode: A in padded [slot][c] layout, 27 chunks = 9 taps x 3 ch-chunks.
// normOut != nullptr: fused per-o-column sum-of-squares (atomicAdd).
#define ROWB 144
#define A_BYTES (128*ROWB)          // 18432
#define SM_STAGE (A_BYTES + 64*ROWB) // 27648
#define SM_TOTAL (2*SM_STAGE)        // 55296
#define NO 64

__device__ __forceinline__ void stage_load(
    uint32_t sb, int slot, const __half* __restrict__ Ag,
    const __half* __restrict__ Bg, int c, int conv_mode, int KB, int o0, int tid)
{
    int t  = c / 3;
    int i0 = (c - t * 3) * 64;
    long arow;
    if (conv_mode) {
        int dy = t / 3 - 1, dx = t - t / 3 * 3 - 1;
        arow = (long)(blockIdx.x + dy + 1) * PADW + 1 + dx;
    } else {
        arow = (long)blockIdx.x * 128;
        i0 = c * 64;
    }
    uint32_t sA = sb + slot * SM_STAGE;
    uint32_t sB = sA + A_BYTES;
    // A: 128 rows x 8 chunks of 16B = 1024 chunks
    #pragma unroll
    for (int it = 0; it < 4; it++) {
        int ck = tid + it * 256;
        int r = ck >> 3, off = ck & 7;
        uint64_t src = __cvta_generic_to_global(Ag + (arow + r) * (long)CC + i0 + off * 8);
        CP16(sA + r * ROWB + off * 16, src);
    }
    // B: 64 rows x 8 chunks = 512 chunks
    #pragma unroll
    for (int it = 0; it < 2; it++) {
        int ck = tid + it * 256;
        int r = ck >> 3, off = ck & 7;
        uint64_t src = __cvta_generic_to_global(Bg + (long)(o0 + r) * KB + c * 64 + off * 8);
        CP16(sB + r * ROWB + off * 16, src);
    }
    asm volatile("cp.async.commit_group;");
}

__global__ __launch_bounds__(256, 4)
void gemm_h(const __half* __restrict__ A, const __half* __restrict__ B,
            void* __restrict__ Cv, long aBatch, long bBatch, long cBatch,
            int KB, int nc, int conv_mode, int outHalf, float* normOut)
{
    extern __shared__ __align__(128) char sm[];
    const uint32_t sb = smem_u32(sm);
    const int tid = threadIdx.x, lane = tid & 31, wid = tid >> 5;
    const int wp = wid & 3, wo = wid >> 2;      // 4 p-quarters x 2 o-halves
    const int b = blockIdx.z, o0 = blockIdx.y * NO;
    const __half* Ag = A + (long)b * aBatch;
    const __half* Bg = B + (long)b * bBatch;

    float acc[2][4][4];
    #pragma unroll
    for (int mf = 0; mf < 2; mf++)
        #pragma unroll
        for (int nf = 0; nf < 4; nf++)
            #pragma unroll
            for (int r = 0; r < 4; r++) acc[mf][nf][r] = 0.f;

    stage_load(sb, 0, Ag, Bg, 0, conv_mode, KB, o0, tid);

    const int t8 = lane >> 3, r8 = lane & 7;
    const int am = (t8 & 1) * 8 + r8, ak = (t8 >> 1) * 8;
    const int bn = (t8 >> 1) * 8 + r8, bk = (t8 & 1) * 8;

    for (int c = 0; c < nc; c++) {
        asm volatile("cp.async.wait_group 0;");
        __syncthreads();
        if (c + 1 < nc)
            stage_load(sb, (c + 1) & 1, Ag, Bg, c + 1, conv_mode, KB, o0, tid);
        uint32_t sA = sb + (c & 1) * SM_STAGE;
        uint32_t sB = sA + A_BYTES;
        #pragma unroll
        for (int ks = 0; ks < 4; ks++) {
            uint32_t a[2][4], bf[2][4];
            #pragma unroll
            for (int mf = 0; mf < 2; mf++) {
                uint32_t addr = sA + (uint32_t)((wp * 32 + mf * 16 + am) * ROWB + (ks * 16 + ak) * 2);
                LDSM_X4(a[mf][0], a[mf][1], a[mf][2], a[mf][3], addr);
            }
            #pragma unroll
            for (int pp = 0; pp < 2; pp++) {
                uint32_t addr = sB + (uint32_t)((wo * 32 + pp * 16 + bn) * ROWB + (ks * 16 + bk) * 2);
                LDSM_X4(bf[pp][0], bf[pp][1], bf[pp][2], bf[pp][3], addr);
            }
            #pragma unroll
            for (int mf = 0; mf < 2; mf++)
                #pragma unroll
                for (int nf = 0; nf < 4; nf++)
                    MMA16816(acc[mf][nf], a[mf], bf[nf >> 1][(nf & 1) * 2],
                             bf[nf >> 1][(nf & 1) * 2 + 1]);
        }
        __syncthreads();
    }

    const int prow = blockIdx.x * 128 + wp * 32 + (lane >> 2);
    const int ocol = o0 + wo * 32 + (lane & 3) * 2;
    if (outHalf) {
        __half* Cb = (__half*)Cv + (long)b * cBatch;
        #pragma unroll
        for (int mf = 0; mf < 2; mf++)
            #pragma unroll
            for (int nf = 0; nf < 4; nf++) {
                int p = prow + mf * 16;
                int o = ocol + nf * 8;
                Cb[(long)o * HW + p]           = __float2half(acc[mf][nf][0]);
                Cb[(long)(o + 1) * HW + p]     = __float2half(acc[mf][nf][1]);
                Cb[(long)o * HW + p + 8]       = __float2half(acc[mf][nf][2]);
                Cb[(long)(o + 1) * HW + p + 8] = __float2half(acc[mf][nf][3]);
            }
    } else {
        float* Cb = (float*)Cv + (long)b * cBatch;
        #pragma unroll
        for (int mf = 0; mf < 2; mf++)
            #pragma unroll
            for (int nf = 0; nf < 4; nf++) {
                int p = prow + mf * 16;
                int o = ocol + nf * 8;
                Cb[(long)o * HW + p]           = acc[mf][nf][0];
                Cb[(long)(o + 1) * HW + p]     = acc[mf][nf][1];
                Cb[(long)o * HW + p + 8]       = acc[mf][nf][2];
                Cb[(long)(o + 1) * HW + p + 8] = acc[mf][nf][3];
            }
    }

    // fused per-o-column sum-of-squares (sum over this block's p rows)
    if (normOut) {
        float s[8];
        #pragma unroll
        for (int i = 0; i < 8; i++) s[i] = 0.f;
        #pragma unroll
        for (int mf = 0; mf < 2; mf++)
            #pragma unroll
            for (int nf = 0; nf < 4; nf++)
                #pragma unroll
                for (int r = 0; r < 4; r++) {
                    float v = acc[mf][nf][r];
                    s[nf * 2 + (r & 1)] += v * v;
                }
        #pragma unroll
        for (int off = 16; off >= 4; off >>= 1)
            #pragma unroll
            for (int i = 0; i < 8; i++)
                s[i] += __shfl_down_sync(0xffffffffu, s[i], off);
        if (lane < 4) {
            #pragma unroll
            for (int nf = 0; nf < 4; nf++)
                #pragma unroll
                for (int par = 0; par < 2; par++) {
                    int o = o0 + wo * 32 + nf * 8 + lane * 2 + par;
                    atomicAdd(&normOut[(long)b * CC + o], s[nf * 2 + par]);
                }
        }
    }
}

// ---------------- producers -------------------------------------------------
// weights -> half, plus zero nkF (runs on s1 before dwconv atomics)
__global__ void conv_h(const float* __restrict__ in, __half* __restrict__ out, int n,
                       float* __restrict__ zeroBuf, int nz) {
    int i = blockIdx.x * 256 + threadIdx.x;
    if (i < n) out[i] = __float2half(in[i]);
    if (i < nz) zeroBuf[i] = 0.f;
}

__global__ void build_w2h(const float* __restrict__ qdw, const float* __restrict__ qw,
                          __half* __restrict__ w2h) {
    int o = blockIdx.x, t = blockIdx.y, i = threadIdx.x;
    __shared__ float dw[CC];
    dw[i] = qdw[(o * CC + i) * 9 + t];
    __syncthreads();
    float acc = 0.f;
    #pragma unroll 4
    for (int m = 0; m < CC; m++) acc += dw[m] * qw[m * CC + i];
    w2h[(long)o * KQ + t * CC + i] = __float2half(acc);
}

// zero guard rows + pad columns of yTpH, plus zero nqF (before conv gemm atomics)
#define NPAD 516
__global__ void pad_zero(__half* __restrict__ yTp, float* __restrict__ nqF) {
    int i = blockIdx.x * 256 + threadIdx.x;
    if (i < NB * CC) nqF[i] = 0.f;
    if (i >= NB * NPAD * CC) return;
    int c = i % CC;
    int r = (i / CC) % NPAD;
    int b = i / (CC * NPAD);
    long slot;
    if (r < 130) slot = r;
    else if (r < 260) slot = (long)PADW * (IMH + 1) + (r - 130);
    else { int j = r - 260; slot = (long)PADW * (1 + (j >> 1)) + ((j & 1) ? PADW - 1 : 0); }
    yTp[((long)b * YSLOTS + slot) * CC + c] = __float2half(0.f);
}

// [b][c][hw] fp32 -> [b][slot][c] half
__global__ void transpose_h(const float* __restrict__ in, long inB,
                            __half* __restrict__ out, long outB, int pad)
{
    __shared__ float t[32][33];
    int b = blockIdx.z, px0 = blockIdx.x * 32, c0 = blockIdx.y * 32;
    int tx = threadIdx.x, ty = threadIdx.y;
    const float* ib = in + (long)b * inB;
    #pragma unroll
    for (int j = 0; j < 4; j++)
        t[ty + j * 8][tx] = ib[(long)(c0 + ty + j * 8) * HW + px0 + tx];
    __syncthreads();
    __half* ob = out + (long)b * outB;
    #pragma unroll
    for (int j = 0; j < 4; j++) {
        int px = px0 + ty + j * 8;
        long slot = pad ? (long)(px >> 7) * PADW + 1 + (px & 127) : px;
        ob[slot * CC + c0 + tx] = __float2half(t[tx][ty + j * 8]);
    }
}

// [b][c][p] half -> [b][p][c] half
__global__ void transpose_hh(const __half* __restrict__ in, __half* __restrict__ out)
{
    __shared__ __half t[32][33];
    int b = blockIdx.z, px0 = blockIdx.x * 32, c0 = blockIdx.y * 32;
    int tx = threadIdx.x, ty = threadIdx.y;
    const __half* ib = in + (long)b * CC * HW;
    #pragma unroll
    for (int j = 0; j < 4; j++)
        t[ty + j * 8][tx] = ib[(long)(c0 + ty + j * 8) * HW + px0 + tx];
    __syncthreads();
    __half* ob = out + (long)b * HW * CC;
    #pragma unroll
    for (int j = 0; j < 4; j++)
        ob[(long)(px0 + ty + j * 8) * CC + c0 + tx] = t[tx][ty + j * 8];
}

// ---------------- depthwise 3x3, half I/O, fused k-norms --------------------
__global__ __launch_bounds__(256)
void dwconv_h(const __half* __restrict__ in, const float* __restrict__ w,
              __half* __restrict__ kout, __half* __restrict__ vout,
              float* __restrict__ nkF)
{
    int g = blockIdx.x * 256 + threadIdx.x;
    int px8 = g & 15;
    int t1 = g >> 4;
    int py = t1 & 127;
    int t2 = t1 >> 7;
    int ch = t2 % (2 * CC);
    int b  = t2 / (2 * CC);
    const __half* base = in + (long)t2 * HW + py * IMW + px8 * 8;

    float w9[9];
    #pragma unroll
    for (int t = 0; t < 9; t++) w9[t] = w[ch * 9 + t];

    float acc[8];
    #pragma unroll
    for (int j = 0; j < 8; j++) acc[j] = 0.f;

    #pragma unroll
    for (int dy = -1; dy <= 1; dy++) {
        int iy = py + dy;
        if (iy < 0 || iy >= IMH) continue;
        const __half* rp = base + dy * IMW;
        float v[10];
        uint4 mid = *(const uint4*)rp;
        const __half* mh = (const __half*)&mid;
        #pragma unroll
        for (int j = 0; j < 8; j++) v[j + 1] = __half2float(mh[j]);
        v[0] = (px8 > 0)  ? __half2float(rp[-1]) : 0.f;
        v[9] = (px8 < 15) ? __half2float(rp[8])  : 0.f;
        int tb = (dy + 1) * 3;
        #pragma unroll
        for (int j = 0; j < 8; j++)
            acc[j] += w9[tb] * v[j] + w9[tb + 1] * v[j + 1] + w9[tb + 2] * v[j + 2];
    }

    __half o8[8];
    #pragma unroll
    for (int j = 0; j < 8; j++) o8[j] = __float2half(acc[j]);
    int cl = (ch < CC) ? ch : ch - CC;
    __half* dst = ((ch < CC) ? kout : vout) + ((long)b * CC + cl) * HW + py * IMW + px8 * 8;
    *(uint4*)dst = *(const uint4*)o8;

    // fused k-norms: each 256-thr block covers exactly one channel (2048 px)
    if (ch < CC) {
        float s = 0.f;
        #pragma unroll
        for (int j = 0; j < 8; j++) s = fmaf(acc[j], acc[j], s);
        #pragma unroll
        for (int off = 16; off > 0; off >>= 1)
            s += __shfl_down_sync(0xffffffffu, s, off);
        __shared__ float ws[8];
        int tid = threadIdx.x;
        if ((tid & 31) == 0) ws[tid >> 5] = s;
        __syncthreads();
        if (tid == 0) {
            float tot = 0.f;
            #pragma unroll
            for (int i = 0; i < 8; i++) tot += ws[i];
            atomicAdd(&nkF[b * CC + ch], tot);
        }
    }
}

// ---------------- gram via mma, double-buffered -----------------------------
#define SK 264
#define GR_STAGE (2*32*SK*2)
#define GR_SMEM  (2*GR_STAGE)

__global__ __launch_bounds__(256)
void gram_mma(const __half* __restrict__ qH, const __half* __restrict__ kH,
              float* __restrict__ Sp)
{
    extern __shared__ __align__(128) char gsm[];
    const uint32_t sb = smem_u32(gsm);
    const int tid = threadIdx.x, lane = tid & 31, w = tid >> 5;
    const int ch = blockIdx.x, h = blockIdx.y, b = blockIdx.z;
    const __half* qb = qH + ((long)b * CC + h * HD) * HW;
    const __half* kb = kH + ((long)b * CC + h * HD) * HW;
    const int k0 = ch * (HW / CHG);

    float acc[2][4][4];
    #pragma unroll
    for (int mt = 0; mt < 2; mt++)
        #pragma unroll
        for (int nf = 0; nf < 4; nf++)
            #pragma unroll
            for (int r = 0; r < 4; r++) acc[mt][nf][r] = 0.f;

    const int t8 = lane >> 3, r8 = lane & 7;
    const int am = (t8 & 1) * 8 + r8, ak = (t8 >> 1) * 8;
    const int bn = (t8 >> 1) * 8 + r8, bk = (t8 & 1) * 8;

#define GR_LOAD(it, s) do {                                                        \
        uint32_t qs = sb + (s) * GR_STAGE, ks_ = qs + 32 * SK * 2;                 \
        int kb0 = (it) * 256;                                                      \
        _Pragma("unroll")                                                          \
        for (int z = 0; z < 4; z++) {                                              \
            int cidx = tid + z * 256;                                              \
            int r = cidx >> 5, c2 = cidx & 31;                                     \
            CP16(qs + r * (SK * 2) + c2 * 16,                                      \
                 __cvta_generic_to_global(qb + (long)r * HW + k0 + kb0 + c2 * 8)); \
            CP16(ks_ + r * (SK * 2) + c2 * 16,                                     \
                 __cvta_generic_to_global(kb + (long)r * HW + k0 + kb0 + c2 * 8)); \
        }                                                                          \
        asm volatile("cp.async.commit_group;");                                    \
    } while (0)

    GR_LOAD(0, 0);
    const int NIT = (HW / CHG) / 256;   // 8
    for (int it = 0; it < NIT; it++) {
        if (it + 1 < NIT) {
            GR_LOAD(it + 1, (it + 1) & 1);
            asm volatile("cp.async.wait_group 1;");
        } else {
            asm volatile("cp.async.wait_group 0;");
        }
        __syncthreads();
        uint32_t qs = sb + (it & 1) * GR_STAGE, ks_ = qs + 32 * SK * 2;
        #pragma unroll
        for (int kst = 0; kst < 2; kst++) {
            int wk = w * 32 + kst * 16;
            uint32_t a[2][4], bf[2][4];
            #pragma unroll
            for (int mt = 0; mt < 2; mt++) {
                uint32_t addr = qs + (uint32_t)(((mt * 16 + am) * SK + wk + ak) * 2);
                LDSM_X4(a[mt][0], a[mt][1], a[mt][2], a[mt][3], addr);
            }
            #pragma unroll
            for (int pp = 0; pp < 2; pp++) {
                uint32_t addr = ks_ + (uint32_t)(((pp * 16 + bn) * SK + wk + bk) * 2);
                LDSM_X4(bf[pp][0], bf[pp][1], bf[pp][2], bf[pp][3], addr);
            }
            #pragma unroll
            for (int mt = 0; mt < 2; mt++)
                #pragma unroll
                for (int nf = 0; nf < 4; nf++)
                    MMA16816(acc[mt][nf], a[mt], bf[nf >> 1][(nf & 1) * 2],
                             bf[nf >> 1][(nf & 1) * 2 + 1]);
        }
        __syncthreads();
    }
#undef GR_LOAD

    float* red = (float*)gsm;
    #pragma unroll
    for (int mt = 0; mt < 2; mt++)
        #pragma unroll
        for (int nf = 0; nf < 4; nf++)
            #pragma unroll
            for (int fr = 0; fr < 4; fr++) {
                int c = mt * 16 + (lane >> 2) + ((fr & 2) ? 8 : 0);
                int d = nf * 8 + (lane & 3) * 2 + (fr & 1);
                red[w * 1024 + c * 32 + d] = acc[mt][nf][fr];
            }
    __syncthreads();
    long base = (((long)b * NHEADS + h) * CHG + ch) * (HD * HD);
    for (int e = tid; e < 32 * HD; e += 256) {
        int c = e / HD, d = e % HD;
        if (c < HD) {
            float s = 0.f;
            #pragma unroll
            for (int ww = 0; ww < 8; ww++) s += red[ww * 1024 + c * 32 + d];
            Sp[base + c * HD + d] = s;
        }
    }
}

// ---------------- softmax + MoH = proj*blockdiag(attn) ----------------------
__global__ void attn_m(const float* __restrict__ Sp, const float* __restrict__ nqF,
                       const float* __restrict__ nkF, const float* __restrict__ temp,
                       const float* __restrict__ proj, __half* __restrict__ MoH) {
    const int h = blockIdx.x, b = blockIdx.y, tid = threadIdx.x;  // 576 threads
    __shared__ float sA[HD][HD + 1];
    __shared__ float snq[HD], snk[HD];
    const long base = ((long)b * NHEADS + h) * CHG;

    float s = 0.f;
    for (int cc = 0; cc < CHG; cc++) s += Sp[(base + cc) * (HD * HD) + tid];

    if (tid < HD) {
        snq[tid] = fmaxf(sqrtf(nqF[b * CC + h * HD + tid]), 1e-12f);
        snk[tid] = fmaxf(sqrtf(nkF[b * CC + h * HD + tid]), 1e-12f);
    }
    __syncthreads();
    {
        int c = tid / HD, d = tid % HD;
        sA[c][d] = s / (snq[c] * snk[d]) * temp[h];
    }
    __syncthreads();
    if (tid < HD) {
        float mx = -1e30f;
        for (int d = 0; d < HD; d++) mx = fmaxf(mx, sA[tid][d]);
        float sum = 0.f;
        for (int d = 0; d < HD; d++) { float e = expf(sA[tid][d] - mx); sA[tid][d] = e; sum += e; }
        float inv = 1.f / sum;
        for (int d = 0; d < HD; d++) sA[tid][d] *= inv;
    }
    __syncthreads();
    for (int l = tid; l < HD * CC; l += 576) {
        int d = l / CC, o = l % CC;
        float acc = 0.f;
        #pragma unroll
        for (int c = 0; c < HD; c++) acc += proj[o * CC + h * HD + c] * sA[c][d];
        MoH[(long)b * CC * CC + (long)o * CC + h * HD + d] = __float2half(acc);
    }
}

// ---------------- launch ----------------------------------------------------
static cudaStream_t g_s1 = nullptr;
static cudaEvent_t  g_e0 = nullptr, g_e1 = nullptr;

extern "C" void kernel_launch(void* const* d_in, const int* in_sizes, int n_in,
                              void* d_out, int out_size) {
    const float* x    = (const float*)d_in[0];
    const float* y    = (const float*)d_in[1];
    const float* temp = (const float*)d_in[2];
    const float* kvw  = (const float*)d_in[3];
    const float* kvdw = (const float*)d_in[4];
    const float* qw   = (const float*)d_in[5];
    const float* qdw  = (const float*)d_in[6];
    const float* proj = (const float*)d_in[7];
    float* out = (float*)d_out;

    __half *xH, *yTpH, *kv1H, *kH, *vcmH, *vH, *qH, *w2H, *kvwH, *MoH;
    float *Sp, *nqF, *nkF;
    cudaGetSymbolAddress((void**)&xH,   g_xH);
    cudaGetSymbolAddress((void**)&yTpH, g_yTpH);
    cudaGetSymbolAddress((void**)&kv1H, g_kv1H);
    cudaGetSymbolAddress((void**)&kH,   g_kH);
    cudaGetSymbolAddress((void**)&vcmH, g_vcmH);
    cudaGetSymbolAddress((void**)&vH,   g_vH);
    cudaGetSymbolAddress((void**)&qH,   g_qH);
    cudaGetSymbolAddress((void**)&w2H,  g_w2H);
    cudaGetSymbolAddress((void**)&kvwH, g_kvwH);
    cudaGetSymbolAddress((void**)&MoH,  g_MoH);
    cudaGetSymbolAddress((void**)&Sp,   g_Sp);
    cudaGetSymbolAddress((void**)&nqF,  g_nqF);
    cudaGetSymbolAddress((void**)&nkF,  g_nkF);

    if (!g_s1) {
        cudaStreamCreateWithFlags(&g_s1, cudaStreamNonBlocking);
        cudaEventCreateWithFlags(&g_e0, cudaEventDisableTiming);
        cudaEventCreateWithFlags(&g_e1, cudaEventDisableTiming);
        cudaFuncSetAttribute(gemm_h, cudaFuncAttributeMaxDynamicSharedMemorySize, SM_TOTAL);
        cudaFuncSetAttribute(gram_mma, cudaFuncAttributeMaxDynamicSharedMemorySize, GR_SMEM);
    }

    // fork: s1 joins the graph
    cudaEventRecord(g_e0, 0);
    cudaStreamWaitEvent(g_s1, g_e0, 0);

    // ---- q-path on stream 0 (conv GEMM = 4th launch for the profiler) ----
    build_w2h<<<dim3(CC, 9), CC>>>(qdw, qw, w2H);                       // 1
    pad_zero<<<(NB * NPAD * CC + 255) / 256, 256>>>(yTpH, nqF);         // 2
    transpose_h<<<dim3(HW / 32, CC / 32, NB), dim3(32, 8)>>>(y, (long)CC * HW,
        yTpH + (long)PADW * CC, (long)YSLOTS * CC, 1);                  // 3
    gemm_h<<<dim3(IMH, 3, NB), 256, SM_TOTAL>>>(yTpH, w2H, qH,
        (long)YSLOTS * CC, 0L, (long)CC * HW, KQ, 27, 1, 1, nqF);       // 4

    // ---- kv-path on s1 (overlaps with conv GEMM) ----
    conv_h<<<(2 * CC * CC + 255) / 256, 256, 0, g_s1>>>(kvw, kvwH, 2 * CC * CC,
                                                        nkF, NB * CC);
    transpose_h<<<dim3(HW / 32, CC / 32, NB), dim3(32, 8), 0, g_s1>>>(x, (long)CC * HW,
        xH, (long)HW * CC, 0);
    gemm_h<<<dim3(128, 6, NB), 256, SM_TOTAL, g_s1>>>(xH, kvwH, kv1H,
        (long)HW * CC, 0L, (long)2 * CC * HW, CC, 3, 0, 1, nullptr);
    dwconv_h<<<NB * 2 * CC * HW / 8 / 256, 256, 0, g_s1>>>(kv1H, kvdw, kH, vcmH, nkF);
    transpose_hh<<<dim3(HW / 32, CC / 32, NB), dim3(32, 8), 0, g_s1>>>(vcmH, vH);

    // join: stream 0 waits for kv-path
    cudaEventRecord(g_e1, g_s1);
    cudaStreamWaitEvent(0, g_e1, 0);

    // ---- tail on stream 0 ----
    gram_mma<<<dim3(CHG, NHEADS, NB), 256, GR_SMEM>>>(qH, kH, Sp);
    attn_m<<<dim3(NHEADS, NB), 576>>>(Sp, nqF, nkF, temp, proj, MoH);
    gemm_h<<<dim3(128, 3, NB), 256, SM_TOTAL>>>(vH, MoH, out,
        (long)HW * CC, (long)CC * CC, (long)CC * HW, CC, 3, 0, 0, nullptr);
}

// round 17
// speedup vs baseline: 1.0204x; 1.0204x over previous
#include <cuda_runtime.h>
#include <cuda_fp16.h>
#include <math.h>
#include <stdint.h>

#define HW    16384
#define IMW   128
#define IMH   128
#define CC    192
#define NB    8
#define NHEADS 8
#define HD    24
#define CHG   8
#define KQ    (9*CC)            // 1728
#define PADW  130
#define PADHW (IMH*PADW)        // 16640
#define YSLOTS (PADHW + 2*PADW) // guard rows top+bottom

// ---------------- scratch ---------------------------------------------------
__device__ __align__(1024) __half g_xH  [(size_t)NB*HW*CC];
__device__ __align__(1024) __half g_yTpH[(size_t)NB*YSLOTS*CC];
__device__ __align__(1024) __half g_kv1H[(size_t)NB*2*CC*HW];
__device__ __align__(1024) __half g_kH  [(size_t)NB*CC*HW + 16*HW];
__device__ __align__(1024) __half g_vcmH[(size_t)NB*CC*HW];
__device__ __align__(1024) __half g_vH  [(size_t)NB*HW*CC];
__device__ __align__(1024) __half g_qH  [(size_t)NB*CC*HW + 16*HW];
__device__ __align__(1024) __half g_w2H [(size_t)CC*KQ];
__device__ __align__(1024) __half g_kvwH[2*CC*CC];
__device__ __align__(1024) __half g_MoH [(size_t)NB*CC*CC];
__device__ float g_Sp [(size_t)NB*NHEADS*CHG*HD*HD];
__device__ float g_nqF[(size_t)NB*CC];
__device__ float g_nkF[(size_t)NB*CC];

__device__ __forceinline__ uint32_t smem_u32(const void* p) {
    uint32_t a;
    asm("{ .reg .u64 t; cvta.to.shared.u64 t, %1; cvt.u32.u64 %0, t; }"
        : "=r"(a) : "l"(p));
    return a;
}

#define LDSM_X4(r0, r1, r2, r3, addr) \
    asm volatile("ldmatrix.sync.aligned.m8n8.x4.shared.b16 {%0,%1,%2,%3}, [%4];" \
                 : "=r"(r0), "=r"(r1), "=r"(r2), "=r"(r3) : "r"(addr))

#define MMA16816(d, a, b0v, b1v) \
    asm volatile("mma.sync.aligned.m16n8k16.row.col.f32.f16.f16.f32 " \
                 "{%0,%1,%2,%3}, {%4,%5,%6,%7}, {%8,%9}, {%0,%1,%2,%3};" \
                 : "+f"((d)[0]), "+f"((d)[1]), "+f"((d)[2]), "+f"((d)[3]) \
                 : "r"((a)[0]), "r"((a)[1]), "r"((a)[2]), "r"((a)[3]), \
                   "r"(b0v), "r"(b1v))

#define CP16(dst, src) \
    asm volatile("cp.async.cg.shared.global [%0], [%1], 16;" \
                 :: "r"(dst), "l"(src))

// ---------------- fp16 mma GEMM: 128p x 96o tile, BK=64, 3 blocks/SM --------
// C[o][p] = sum_k A[p][k]*B[o][k]; 256 thr, 2-stage cp.async double buffer.
// 8 warps = 4 p-quarters (32 rows) x 2 o-halves (48 cols); acc 2x6x4.
// Rows stored with 144B stride -> conflict-free ldmatrix.
// conv_mode: A in padded [slot][c] layout, 27 chunks = 9 taps x 3 ch-chunks.
// normOut != nullptr: fused per-o-column sum-of-squares (atomicAdd).
#define ROWB 144
#define A_BYTES (128*ROWB)
#define SM_STAGE (A_BYTES + 96*ROWB)
#define SM_TOTAL (2*SM_STAGE)
#define NO 96

__device__ __forceinline__ void stage_load(
    uint32_t sb, int slot, const __half* __restrict__ Ag,
    const __half* __restrict__ Bg, int c, int conv_mode, int KB, int o0, int tid)
{
    int t  = c / 3;
    int i0 = (c - t * 3) * 64;
    long arow;
    if (conv_mode) {
        int dy = t / 3 - 1, dx = t - t / 3 * 3 - 1;
        arow = (long)(blockIdx.x + dy + 1) * PADW + 1 + dx;
    } else {
        arow = (long)blockIdx.x * 128;
        i0 = c * 64;
    }
    uint32_t sA = sb + slot * SM_STAGE;
    uint32_t sB = sA + A_BYTES;
    #pragma unroll
    for (int it = 0; it < 4; it++) {
        int ck = tid + it * 256;
        int r = ck >> 3, off = ck & 7;
        uint64_t src = __cvta_generic_to_global(Ag + (arow + r) * (long)CC + i0 + off * 8);
        CP16(sA + r * ROWB + off * 16, src);
    }
    #pragma unroll
    for (int it = 0; it < 3; it++) {
        int ck = tid + it * 256;
        int r = ck >> 3, off = ck & 7;
        uint64_t src = __cvta_generic_to_global(Bg + (long)(o0 + r) * KB + c * 64 + off * 8);
        CP16(sB + r * ROWB + off * 16, src);
    }
    asm volatile("cp.async.commit_group;");
}

__global__ __launch_bounds__(256, 3)
void gemm_h(const __half* __restrict__ A, const __half* __restrict__ B,
            void* __restrict__ Cv, long aBatch, long bBatch, long cBatch,
            int KB, int nc, int conv_mode, int outHalf, float* normOut)
{
    extern __shared__ __align__(128) char sm[];
    const uint32_t sb = smem_u32(sm);
    const int tid = threadIdx.x, lane = tid & 31, wid = tid >> 5;
    const int wp = wid & 3, wo = wid >> 2;
    const int b = blockIdx.z, o0 = blockIdx.y * NO;
    const __half* Ag = A + (long)b * aBatch;
    const __half* Bg = B + (long)b * bBatch;

    float acc[2][6][4];
    #pragma unroll
    for (int mf = 0; mf < 2; mf++)
        #pragma unroll
        for (int nf = 0; nf < 6; nf++)
            #pragma unroll
            for (int r = 0; r < 4; r++) acc[mf][nf][r] = 0.f;

    stage_load(sb, 0, Ag, Bg, 0, conv_mode, KB, o0, tid);

    const int t8 = lane >> 3, r8 = lane & 7;
    const int am = (t8 & 1) * 8 + r8, ak = (t8 >> 1) * 8;
    const int bn = (t8 >> 1) * 8 + r8, bk = (t8 & 1) * 8;

    for (int c = 0; c < nc; c++) {
        asm volatile("cp.async.wait_group 0;");
        __syncthreads();
        if (c + 1 < nc)
            stage_load(sb, (c + 1) & 1, Ag, Bg, c + 1, conv_mode, KB, o0, tid);
        uint32_t sA = sb + (c & 1) * SM_STAGE;
        uint32_t sB = sA + A_BYTES;
        #pragma unroll
        for (int ks = 0; ks < 4; ks++) {
            uint32_t a[2][4], bf[3][4];
            #pragma unroll
            for (int mf = 0; mf < 2; mf++) {
                uint32_t addr = sA + (uint32_t)((wp * 32 + mf * 16 + am) * ROWB + (ks * 16 + ak) * 2);
                LDSM_X4(a[mf][0], a[mf][1], a[mf][2], a[mf][3], addr);
            }
            #pragma unroll
            for (int pp = 0; pp < 3; pp++) {
                uint32_t addr = sB + (uint32_t)((wo * 48 + pp * 16 + bn) * ROWB + (ks * 16 + bk) * 2);
                LDSM_X4(bf[pp][0], bf[pp][1], bf[pp][2], bf[pp][3], addr);
            }
            #pragma unroll
            for (int mf = 0; mf < 2; mf++)
                #pragma unroll
                for (int nf = 0; nf < 6; nf++)
                    MMA16816(acc[mf][nf], a[mf], bf[nf >> 1][(nf & 1) * 2],
                             bf[nf >> 1][(nf & 1) * 2 + 1]);
        }
        __syncthreads();
    }

    const int prow = blockIdx.x * 128 + wp * 32 + (lane >> 2);
    const int ocol = o0 + wo * 48 + (lane & 3) * 2;
    if (outHalf) {
        __half* Cb = (__half*)Cv + (long)b * cBatch;
        #pragma unroll
        for (int mf = 0; mf < 2; mf++)
            #pragma unroll
            for (int nf = 0; nf < 6; nf++) {
                int p = prow + mf * 16;
                int o = ocol + nf * 8;
                Cb[(long)o * HW + p]           = __float2half(acc[mf][nf][0]);
                Cb[(long)(o + 1) * HW + p]     = __float2half(acc[mf][nf][1]);
                Cb[(long)o * HW + p + 8]       = __float2half(acc[mf][nf][2]);
                Cb[(long)(o + 1) * HW + p + 8] = __float2half(acc[mf][nf][3]);
            }
    } else {
        float* Cb = (float*)Cv + (long)b * cBatch;
        #pragma unroll
        for (int mf = 0; mf < 2; mf++)
            #pragma unroll
            for (int nf = 0; nf < 6; nf++) {
                int p = prow + mf * 16;
                int o = ocol + nf * 8;
                Cb[(long)o * HW + p]           = acc[mf][nf][0];
                Cb[(long)(o + 1) * HW + p]     = acc[mf][nf][1];
                Cb[(long)o * HW + p + 8]       = acc[mf][nf][2];
                Cb[(long)(o + 1) * HW + p + 8] = acc[mf][nf][3];
            }
    }

    // fused per-o-column sum-of-squares (sum over this block's p rows)
    if (normOut) {
        float s[12];
        #pragma unroll
        for (int i = 0; i < 12; i++) s[i] = 0.f;
        #pragma unroll
        for (int mf = 0; mf < 2; mf++)
            #pragma unroll
            for (int nf = 0; nf < 6; nf++)
                #pragma unroll
                for (int r = 0; r < 4; r++) {
                    float v = acc[mf][nf][r];
                    s[nf * 2 + (r & 1)] += v * v;
                }
        #pragma unroll
        for (int off = 16; off >= 4; off >>= 1)
            #pragma unroll
            for (int i = 0; i < 12; i++)
                s[i] += __shfl_down_sync(0xffffffffu, s[i], off);
        if (lane < 4) {
            #pragma unroll
            for (int nf = 0; nf < 6; nf++)
                #pragma unroll
                for (int par = 0; par < 2; par++) {
                    int o = o0 + wo * 48 + nf * 8 + lane * 2 + par;
                    atomicAdd(&normOut[(long)b * CC + o], s[nf * 2 + par]);
                }
        }
    }
}

// ---------------- producers -------------------------------------------------
__global__ void conv_h(const float* __restrict__ in, __half* __restrict__ out, int n,
                       float* __restrict__ zeroBuf, int nz) {
    int i = blockIdx.x * 256 + threadIdx.x;
    if (i < n) out[i] = __float2half(in[i]);
    if (i < nz) zeroBuf[i] = 0.f;
}

__global__ void build_w2h(const float* __restrict__ qdw, const float* __restrict__ qw,
                          __half* __restrict__ w2h) {
    int o = blockIdx.x, t = blockIdx.y, i = threadIdx.x;
    __shared__ float dw[CC];
    dw[i] = qdw[(o * CC + i) * 9 + t];
    __syncthreads();
    float acc = 0.f;
    #pragma unroll 4
    for (int m = 0; m < CC; m++) acc += dw[m] * qw[m * CC + i];
    w2h[(long)o * KQ + t * CC + i] = __float2half(acc);
}

#define NPAD 516
__global__ void pad_zero(__half* __restrict__ yTp, float* __restrict__ nqF) {
    int i = blockIdx.x * 256 + threadIdx.x;
    if (i < NB * CC) nqF[i] = 0.f;
    if (i >= NB * NPAD * CC) return;
    int c = i % CC;
    int r = (i / CC) % NPAD;
    int b = i / (CC * NPAD);
    long slot;
    if (r < 130) slot = r;
    else if (r < 260) slot = (long)PADW * (IMH + 1) + (r - 130);
    else { int j = r - 260; slot = (long)PADW * (1 + (j >> 1)) + ((j & 1) ? PADW - 1 : 0); }
    yTp[((long)b * YSLOTS + slot) * CC + c] = __float2half(0.f);
}

// [b][c][hw] fp32 -> [b][slot][c] half, half2 stores
__global__ void transpose_h(const float* __restrict__ in, long inB,
                            __half* __restrict__ out, long outB, int pad)
{
    __shared__ float t[32][33];      // t[c][px]
    int b = blockIdx.z, px0 = blockIdx.x * 32, c0 = blockIdx.y * 32;
    int tx = threadIdx.x, ty = threadIdx.y;
    const float* ib = in + (long)b * inB;
    #pragma unroll
    for (int j = 0; j < 4; j++)
        t[ty + j * 8][tx] = ib[(long)(c0 + ty + j * 8) * HW + px0 + tx];
    __syncthreads();
    __half* ob = out + (long)b * outB;
    int tid = ty * 32 + tx;          // 0..255
    int c2 = tid & 15;               // half2 column pair
    int r0 = tid >> 4;               // 0..15
    #pragma unroll
    for (int j = 0; j < 2; j++) {
        int r = r0 + j * 16;
        int px = px0 + r;
        long slot = pad ? (long)(px >> 7) * PADW + 1 + (px & 127) : px;
        __half2 v = __floats2half2_rn(t[c2 * 2][r], t[c2 * 2 + 1][r]);
        *(__half2*)&ob[slot * CC + c0 + c2 * 2] = v;
    }
}

// [b][c][p] half -> [b][p][c] half
__global__ void transpose_hh(const __half* __restrict__ in, __half* __restrict__ out)
{
    __shared__ __half t[32][33];
    int b = blockIdx.z, px0 = blockIdx.x * 32, c0 = blockIdx.y * 32;
    int tx = threadIdx.x, ty = threadIdx.y;
    const __half* ib = in + (long)b * CC * HW;
    #pragma unroll
    for (int j = 0; j < 4; j++)
        t[ty + j * 8][tx] = ib[(long)(c0 + ty + j * 8) * HW + px0 + tx];
    __syncthreads();
    __half* ob = out + (long)b * HW * CC;
    #pragma unroll
    for (int j = 0; j < 4; j++)
        ob[(long)(px0 + ty + j * 8) * CC + c0 + tx] = t[tx][ty + j * 8];
}

// ---------------- depthwise 3x3, half I/O, fused k-norms --------------------
__global__ __launch_bounds__(256)
void dwconv_h(const __half* __restrict__ in, const float* __restrict__ w,
              __half* __restrict__ kout, __half* __restrict__ vout,
              float* __restrict__ nkF)
{
    int g = blockIdx.x * 256 + threadIdx.x;
    int px8 = g & 15;
    int t1 = g >> 4;
    int py = t1 & 127;
    int t2 = t1 >> 7;
    int ch = t2 % (2 * CC);
    int b  = t2 / (2 * CC);
    const __half* base = in + (long)t2 * HW + py * IMW + px8 * 8;

    float w9[9];
    #pragma unroll
    for (int t = 0; t < 9; t++) w9[t] = w[ch * 9 + t];

    float acc[8];
    #pragma unroll
    for (int j = 0; j < 8; j++) acc[j] = 0.f;

    #pragma unroll
    for (int dy = -1; dy <= 1; dy++) {
        int iy = py + dy;
        if (iy < 0 || iy >= IMH) continue;
        const __half* rp = base + dy * IMW;
        float v[10];
        uint4 mid = *(const uint4*)rp;
        const __half* mh = (const __half*)&mid;
        #pragma unroll
        for (int j = 0; j < 8; j++) v[j + 1] = __half2float(mh[j]);
        v[0] = (px8 > 0)  ? __half2float(rp[-1]) : 0.f;
        v[9] = (px8 < 15) ? __half2float(rp[8])  : 0.f;
        int tb = (dy + 1) * 3;
        #pragma unroll
        for (int j = 0; j < 8; j++)
            acc[j] += w9[tb] * v[j] + w9[tb + 1] * v[j + 1] + w9[tb + 2] * v[j + 2];
    }

    __half o8[8];
    #pragma unroll
    for (int j = 0; j < 8; j++) o8[j] = __float2half(acc[j]);
    int cl = (ch < CC) ? ch : ch - CC;
    __half* dst = ((ch < CC) ? kout : vout) + ((long)b * CC + cl) * HW + py * IMW + px8 * 8;
    *(uint4*)dst = *(const uint4*)o8;

    if (ch < CC) {
        float s = 0.f;
        #pragma unroll
        for (int j = 0; j < 8; j++) s = fmaf(acc[j], acc[j], s);
        #pragma unroll
        for (int off = 16; off > 0; off >>= 1)
            s += __shfl_down_sync(0xffffffffu, s, off);
        __shared__ float ws[8];
        int tid = threadIdx.x;
        if ((tid & 31) == 0) ws[tid >> 5] = s;
        __syncthreads();
        if (tid == 0) {
            float tot = 0.f;
            #pragma unroll
            for (int i = 0; i < 8; i++) tot += ws[i];
            atomicAdd(&nkF[b * CC + ch], tot);
        }
    }
}

// ---------------- gram via mma, double-buffered -----------------------------
#define SK 264
#define GR_STAGE (2*32*SK*2)
#define GR_SMEM  (2*GR_STAGE)

__global__ __launch_bounds__(256)
void gram_mma(const __half* __restrict__ qH, const __half* __restrict__ kH,
              float* __restrict__ Sp)
{
    extern __shared__ __align__(128) char gsm[];
    const uint32_t sb = smem_u32(gsm);
    const int tid = threadIdx.x, lane = tid & 31, w = tid >> 5;
    const int ch = blockIdx.x, h = blockIdx.y, b = blockIdx.z;
    const __half* qb = qH + ((long)b * CC + h * HD) * HW;
    const __half* kb = kH + ((long)b * CC + h * HD) * HW;
    const int k0 = ch * (HW / CHG);

    float acc[2][4][4];
    #pragma unroll
    for (int mt = 0; mt < 2; mt++)
        #pragma unroll
        for (int nf = 0; nf < 4; nf++)
            #pragma unroll
            for (int r = 0; r < 4; r++) acc[mt][nf][r] = 0.f;

    const int t8 = lane >> 3, r8 = lane & 7;
    const int am = (t8 & 1) * 8 + r8, ak = (t8 >> 1) * 8;
    const int bn = (t8 >> 1) * 8 + r8, bk = (t8 & 1) * 8;

#define GR_LOAD(it, s) do {                                                        \
        uint32_t qs = sb + (s) * GR_STAGE, ks_ = qs + 32 * SK * 2;                 \
        int kb0 = (it) * 256;                                                      \
        _Pragma("unroll")                                                          \
        for (int z = 0; z < 4; z++) {                                              \
            int cidx = tid + z * 256;                                              \
            int r = cidx >> 5, c2 = cidx & 31;                                     \
            CP16(qs + r * (SK * 2) + c2 * 16,                                      \
                 __cvta_generic_to_global(qb + (long)r * HW + k0 + kb0 + c2 * 8)); \
            CP16(ks_ + r * (SK * 2) + c2 * 16,                                     \
                 __cvta_generic_to_global(kb + (long)r * HW + k0 + kb0 + c2 * 8)); \
        }                                                                          \
        asm volatile("cp.async.commit_group;");                                    \
    } while (0)

    GR_LOAD(0, 0);
    const int NIT = (HW / CHG) / 256;   // 8
    for (int it = 0; it < NIT; it++) {
        if (it + 1 < NIT) {
            GR_LOAD(it + 1, (it + 1) & 1);
            asm volatile("cp.async.wait_group 1;");
        } else {
            asm volatile("cp.async.wait_group 0;");
        }
        __syncthreads();
        uint32_t qs = sb + (it & 1) * GR_STAGE, ks_ = qs + 32 * SK * 2;
        #pragma unroll
        for (int kst = 0; kst < 2; kst++) {
            int wk = w * 32 + kst * 16;
            uint32_t a[2][4], bf[2][4];
            #pragma unroll
            for (int mt = 0; mt < 2; mt++) {
                uint32_t addr = qs + (uint32_t)(((mt * 16 + am) * SK + wk + ak) * 2);
                LDSM_X4(a[mt][0], a[mt][1], a[mt][2], a[mt][3], addr);
            }
            #pragma unroll
            for (int pp = 0; pp < 2; pp++) {
                uint32_t addr = ks_ + (uint32_t)(((pp * 16 + bn) * SK + wk + bk) * 2);
                LDSM_X4(bf[pp][0], bf[pp][1], bf[pp][2], bf[pp][3], addr);
            }
            #pragma unroll
            for (int mt = 0; mt < 2; mt++)
                #pragma unroll
                for (int nf = 0; nf < 4; nf++)
                    MMA16816(acc[mt][nf], a[mt], bf[nf >> 1][(nf & 1) * 2],
                             bf[nf >> 1][(nf & 1) * 2 + 1]);
        }
        __syncthreads();
    }
#undef GR_LOAD

    float* red = (float*)gsm;
    #pragma unroll
    for (int mt = 0; mt < 2; mt++)
        #pragma unroll
        for (int nf = 0; nf < 4; nf++)
            #pragma unroll
            for (int fr = 0; fr < 4; fr++) {
                int c = mt * 16 + (lane >> 2) + ((fr & 2) ? 8 : 0);
                int d = nf * 8 + (lane & 3) * 2 + (fr & 1);
                red[w * 1024 + c * 32 + d] = acc[mt][nf][fr];
            }
    __syncthreads();
    long base = (((long)b * NHEADS + h) * CHG + ch) * (HD * HD);
    for (int e = tid; e < 32 * HD; e += 256) {
        int c = e / HD, d = e % HD;
        if (c < HD) {
            float s = 0.f;
            #pragma unroll
            for (int ww = 0; ww < 8; ww++) s += red[ww * 1024 + c * 32 + d];
            Sp[base + c * HD + d] = s;
        }
    }
}

// ---------------- softmax + MoH = proj*blockdiag(attn) ----------------------
__global__ void attn_m(const float* __restrict__ Sp, const float* __restrict__ nqF,
                       const float* __restrict__ nkF, const float* __restrict__ temp,
                       const float* __restrict__ proj, __half* __restrict__ MoH) {
    const int h = blockIdx.x, b = blockIdx.y, tid = threadIdx.x;  // 576 threads
    __shared__ float sA[HD][HD + 1];
    __shared__ float snq[HD], snk[HD];
    const long base = ((long)b * NHEADS + h) * CHG;

    float s = 0.f;
    for (int cc = 0; cc < CHG; cc++) s += Sp[(base + cc) * (HD * HD) + tid];

    if (tid < HD) {
        snq[tid] = fmaxf(sqrtf(nqF[b * CC + h * HD + tid]), 1e-12f);
        snk[tid] = fmaxf(sqrtf(nkF[b * CC + h * HD + tid]), 1e-12f);
    }
    __syncthreads();
    {
        int c = tid / HD, d = tid % HD;
        sA[c][d] = s / (snq[c] * snk[d]) * temp[h];
    }
    __syncthreads();
    if (tid < HD) {
        float mx = -1e30f;
        for (int d = 0; d < HD; d++) mx = fmaxf(mx, sA[tid][d]);
        float sum = 0.f;
        for (int d = 0; d < HD; d++) { float e = expf(sA[tid][d] - mx); sA[tid][d] = e; sum += e; }
        float inv = 1.f / sum;
        for (int d = 0; d < HD; d++) sA[tid][d] *= inv;
    }
    __syncthreads();
    for (int l = tid; l < HD * CC; l += 576) {
        int d = l / CC, o = l % CC;
        float acc = 0.f;
        #pragma unroll
        for (int c = 0; c < HD; c++) acc += proj[o * CC + h * HD + c] * sA[c][d];
        MoH[(long)b * CC * CC + (long)o * CC + h * HD + d] = __float2half(acc);
    }
}

// ---------------- launch ----------------------------------------------------
static cudaStream_t g_s1 = nullptr;
static cudaEvent_t  g_e0 = nullptr, g_e1 = nullptr;

extern "C" void kernel_launch(void* const* d_in, const int* in_sizes, int n_in,
                              void* d_out, int out_size) {
    const float* x    = (const float*)d_in[0];
    const float* y    = (const float*)d_in[1];
    const float* temp = (const float*)d_in[2];
    const float* kvw  = (const float*)d_in[3];
    const float* kvdw = (const float*)d_in[4];
    const float* qw   = (const float*)d_in[5];
    const float* qdw  = (const float*)d_in[6];
    const float* proj = (const float*)d_in[7];
    float* out = (float*)d_out;

    __half *xH, *yTpH, *kv1H, *kH, *vcmH, *vH, *qH, *w2H, *kvwH, *MoH;
    float *Sp, *nqF, *nkF;
    cudaGetSymbolAddress((void**)&xH,   g_xH);
    cudaGetSymbolAddress((void**)&yTpH, g_yTpH);
    cudaGetSymbolAddress((void**)&kv1H, g_kv1H);
    cudaGetSymbolAddress((void**)&kH,   g_kH);
    cudaGetSymbolAddress((void**)&vcmH, g_vcmH);
    cudaGetSymbolAddress((void**)&vH,   g_vH);
    cudaGetSymbolAddress((void**)&qH,   g_qH);
    cudaGetSymbolAddress((void**)&w2H,  g_w2H);
    cudaGetSymbolAddress((void**)&kvwH, g_kvwH);
    cudaGetSymbolAddress((void**)&MoH,  g_MoH);
    cudaGetSymbolAddress((void**)&Sp,   g_Sp);
    cudaGetSymbolAddress((void**)&nqF,  g_nqF);
    cudaGetSymbolAddress((void**)&nkF,  g_nkF);

    if (!g_s1) {
        cudaStreamCreateWithFlags(&g_s1, cudaStreamNonBlocking);
        cudaEventCreateWithFlags(&g_e0, cudaEventDisableTiming);
        cudaEventCreateWithFlags(&g_e1, cudaEventDisableTiming);
        cudaFuncSetAttribute(gemm_h, cudaFuncAttributeMaxDynamicSharedMemorySize, SM_TOTAL);
        cudaFuncSetAttribute(gram_mma, cudaFuncAttributeMaxDynamicSharedMemorySize, GR_SMEM);
    }

    // fork: s1 joins the graph
    cudaEventRecord(g_e0, 0);
    cudaStreamWaitEvent(g_s1, g_e0, 0);

    // ---- q-path on stream 0 (conv GEMM = 4th launch for the profiler) ----
    build_w2h<<<dim3(CC, 9), CC>>>(qdw, qw, w2H);                       // 1
    pad_zero<<<(NB * NPAD * CC + 255) / 256, 256>>>(yTpH, nqF);         // 2
    transpose_h<<<dim3(HW / 32, CC / 32, NB), dim3(32, 8)>>>(y, (long)CC * HW,
        yTpH + (long)PADW * CC, (long)YSLOTS * CC, 1);                  // 3
    gemm_h<<<dim3(IMH, 2, NB), 256, SM_TOTAL>>>(yTpH, w2H, qH,
        (long)YSLOTS * CC, 0L, (long)CC * HW, KQ, 27, 1, 1, nqF);       // 4

    // ---- kv-path on s1 (overlaps with conv GEMM) ----
    conv_h<<<(2 * CC * CC + 255) / 256, 256, 0, g_s1>>>(kvw, kvwH, 2 * CC * CC,
                                                        nkF, NB * CC);
    transpose_h<<<dim3(HW / 32, CC / 32, NB), dim3(32, 8), 0, g_s1>>>(x, (long)CC * HW,
        xH, (long)HW * CC, 0);
    gemm_h<<<dim3(128, 4, NB), 256, SM_TOTAL, g_s1>>>(xH, kvwH, kv1H,
        (long)HW * CC, 0L, (long)2 * CC * HW, CC, 3, 0, 1, nullptr);
    dwconv_h<<<NB * 2 * CC * HW / 8 / 256, 256, 0, g_s1>>>(kv1H, kvdw, kH, vcmH, nkF);
    transpose_hh<<<dim3(HW / 32, CC / 32, NB), dim3(32, 8), 0, g_s1>>>(vcmH, vH);

    // join: stream 0 waits for kv-path
    cudaEventRecord(g_e1, g_s1);
    cudaStreamWaitEvent(0, g_e1, 0);

    // ---- tail on stream 0 ----
    gram_mma<<<dim3(CHG, NHEADS, NB), 256, GR_SMEM>>>(qH, kH, Sp);
    attn_m<<<dim3(NHEADS, NB), 576>>>(Sp, nqF, nkF, temp, proj, MoH);
    gemm_h<<<dim3(128, 2, NB), 256, SM_TOTAL>>>(vH, MoH, out,
        (long)HW * CC, (long)CC * CC, (long)CC * HW, CC, 3, 0, 0, nullptr);
}